// round 3
// baseline (speedup 1.0000x reference)
#include <cuda_runtime.h>
#include <math.h>
#include <stdint.h>

// Problem constants
#define NROWS 16384            // B*H*W = 16*32*32
#define NE    16384            // codebook entries
#define D     256              // embed dim
#define HW    1024             // H*W
#define CHW   262144           // C*H*W

// GEMM tiling
#define TM 128
#define TN 128
#define KC 32
#define SPLITS 2
#define TILES_PER_SPLIT ((NE / TN) / SPLITS)   // 64

// Output layout (concatenated reference tuple, float32):
// z_q_out (4194304) | loss (1) | perplexity (1) | min_encoding (16384*16384) | idx (16384)
#define ZQ_OFF   0ULL
#define LOSS_OFF 4194304ULL
#define PERP_OFF 4194305ULL
#define OH_OFF   4194306ULL
#define IDX_OFF  272629762ULL   // 4194306 + 268435456

// Scratch (no device allocation allowed -> __device__ globals)
__device__ float  g_enorm[NE];
__device__ float  g_znorm[NROWS];
__device__ float  g_bestv[SPLITS][NROWS];
__device__ int    g_besti[SPLITS][NROWS];
__device__ int    g_idx[NROWS];
__device__ int    g_count[NE];
__device__ double g_losspart[16384];

// ---------------------------------------------------------------------------
// Zero the whole output buffer (poisoned to 0xAA). float4 grid-stride.
// ---------------------------------------------------------------------------
__global__ void k_zero(float4* __restrict__ out4, long long n4,
                       float* __restrict__ out, long long total) {
    long long i = (long long)blockIdx.x * blockDim.x + threadIdx.x;
    long long stride = (long long)gridDim.x * blockDim.x;
    float4 zz = make_float4(0.f, 0.f, 0.f, 0.f);
    for (long long p = i; p < n4; p += stride) out4[p] = zz;
    long long t0 = n4 * 4;
    if (i < total - t0) out[t0 + i] = 0.f;
}

__global__ void k_zero_counts() {
    int i = blockIdx.x * blockDim.x + threadIdx.x;
    if (i < NE) g_count[i] = 0;
}

// ---------------------------------------------------------------------------
// ||e_j||^2 : STRICT reference replication — fl(v*v) then sequential fl adds,
// k ascending (XLA:CPU minor-dim reduce = scalar sequential loop).
// One thread per codebook row.
// ---------------------------------------------------------------------------
__global__ void k_enorm(const float* __restrict__ emb) {
    int r = blockIdx.x * blockDim.x + threadIdx.x;
    if (r >= NE) return;
    const float* row = emb + (size_t)r * D;
    float s = 0.f;
    for (int k = 0; k < D; k++) {
        float v = row[k];
        s = __fadd_rn(s, __fmul_rn(v, v));
    }
    g_enorm[r] = s;
}

// ---------------------------------------------------------------------------
// ||z_i||^2 : same strict sequential order over c = 0..255.
// zf[row][c] = z[b*CHW + c*HW + hw], row = b*1024 + hw.
// Coalesced across threads (consecutive rows -> consecutive hw).
// ---------------------------------------------------------------------------
__global__ void k_znorm(const float* __restrict__ z) {
    int r = blockIdx.x * blockDim.x + threadIdx.x;
    if (r >= NROWS) return;
    int b  = r >> 10;
    int hw = r & 1023;
    const float* base = z + (size_t)b * CHW + hw;
    float s = 0.f;
    for (int c = 0; c < D; c++) {
        float v = base[(size_t)c * HW];
        s = __fadd_rn(s, __fmul_rn(v, v));
    }
    g_znorm[r] = s;
}

// ---------------------------------------------------------------------------
// Fused fp32 distance GEMM + running argmin, replicating reference rounding:
//   m_ij = sequential-k fma dot (Eigen gebp order)
//   d    = fl( fl(S_i + E_j) - 2*m_ij )
//   argmin: strict <, ascending j, lowest-index tie-break.
// Block: 128 rows x 128-code tiles, 8x8 per thread, K chunked by 32.
// ---------------------------------------------------------------------------
__launch_bounds__(256, 2)
__global__ void k_dist_argmin(const float* __restrict__ z,
                              const float* __restrict__ emb) {
    __shared__ float zs[KC][TM];        // 16 KB
    __shared__ float es[KC][TN + 1];    // stride 129 -> conflict-free col stores
    __shared__ float en_s[TN];
    __shared__ float zn_s[TM];

    int tid = threadIdx.x;
    int tx = tid & 15;    // code group (8 codes)
    int ty = tid >> 4;    // row group  (8 rows)

    int row0 = blockIdx.x * TM;
    int b    = row0 >> 10;       // row / 1024
    int hw0  = row0 & 1023;
    const float* zb = z + (size_t)b * CHW + hw0;   // zf[row0+m][c] = zb[c*1024 + m]

    if (tid < TM) zn_s[tid] = g_znorm[row0 + tid];

    float bestv[8];
    int   besti[8];
    #pragma unroll
    for (int i = 0; i < 8; i++) { bestv[i] = INFINITY; besti[i] = 0x7fffffff; }

    int split  = blockIdx.y;
    int j0base = split * (TILES_PER_SPLIT * TN);

    for (int t = 0; t < TILES_PER_SPLIT; t++) {
        int j0 = j0base + t * TN;
        __syncthreads();                         // protect en_s / smem reuse
        if (tid < TN) en_s[tid] = g_enorm[j0 + tid];

        float acc[8][8];
        #pragma unroll
        for (int i = 0; i < 8; i++)
            #pragma unroll
            for (int j = 0; j < 8; j++) acc[i][j] = 0.f;

        for (int c0 = 0; c0 < D; c0 += KC) {
            __syncthreads();
            // z tile: 128 rows x 32 k. Coalesced along m.
            #pragma unroll
            for (int l = 0; l < 16; l++) {
                int id = l * 256 + tid;
                int k = id >> 7;
                int m = id & 127;
                zs[k][m] = zb[(size_t)(c0 + k) * HW + m];
            }
            // e tile: 128 codes x 32 k, float4 along k, store transposed [k][n]
            #pragma unroll
            for (int l = 0; l < 4; l++) {
                int id = l * 256 + tid;      // float4 index, 0..1023
                int n  = id >> 3;
                int k4 = id & 7;
                float4 v = *(const float4*)(emb + (size_t)(j0 + n) * D + c0 + k4 * 4);
                es[k4 * 4 + 0][n] = v.x;
                es[k4 * 4 + 1][n] = v.y;
                es[k4 * 4 + 2][n] = v.z;
                es[k4 * 4 + 3][n] = v.w;
            }
            __syncthreads();
            // k ascending, single accumulator per (i,j) -> sequential fma chain
            #pragma unroll
            for (int k = 0; k < KC; k++) {
                float a[8], bf[8];
                *(float4*)&a[0] = *(const float4*)&zs[k][ty * 8];
                *(float4*)&a[4] = *(const float4*)&zs[k][ty * 8 + 4];
                #pragma unroll
                for (int j = 0; j < 8; j++) bf[j] = es[k][tx * 8 + j];
                #pragma unroll
                for (int i = 0; i < 8; i++)
                    #pragma unroll
                    for (int j = 0; j < 8; j++)
                        acc[i][j] = fmaf(a[i], bf[j], acc[i][j]);
            }
        }
        // argmin update with EXACT reference rounding:
        // d = fl( fl(S + E) - 2*m );  strict < keeps the first (lowest) index
        #pragma unroll
        for (int i = 0; i < 8; i++) {
            float S = zn_s[ty * 8 + i];
            #pragma unroll
            for (int j = 0; j < 8; j++) {
                int n = tx * 8 + j;
                float tSE = __fadd_rn(S, en_s[n]);
                float d   = __fadd_rn(tSE, __fmul_rn(-2.0f, acc[i][j]));
                if (d < bestv[i]) { bestv[i] = d; besti[i] = j0 + n; }
            }
        }
    }

    // Cross-thread reduction per row (16 candidates/row), reusing smem.
    __syncthreads();
    float (*rv)[17] = (float(*)[17])zs;   // 128*17*4 = 8.7KB <= 16KB
    int   (*ri)[17] = (int(*)[17])es;
    #pragma unroll
    for (int i = 0; i < 8; i++) {
        rv[ty * 8 + i][tx] = bestv[i];
        ri[ty * 8 + i][tx] = besti[i];
    }
    __syncthreads();
    if (tid < TM) {
        float bv = rv[tid][0]; int bi = ri[tid][0];
        #pragma unroll
        for (int x = 1; x < 16; x++) {
            float v = rv[tid][x]; int ii = ri[tid][x];
            if (v < bv || (v == bv && ii < bi)) { bv = v; bi = ii; }
        }
        g_bestv[split][row0 + tid] = bv;
        g_besti[split][row0 + tid] = bi;
    }
}

// ---------------------------------------------------------------------------
// Combine splits, emit idx (as float), one-hot scatter, histogram
// ---------------------------------------------------------------------------
__global__ void k_finalize(float* __restrict__ out) {
    int r = blockIdx.x * blockDim.x + threadIdx.x;
    if (r >= NROWS) return;
    float v0 = g_bestv[0][r]; int i0 = g_besti[0][r];
    float v1 = g_bestv[1][r]; int i1 = g_besti[1][r];
    int idx = (v1 < v0) ? i1 : i0;   // tie -> split 0 (lower indices)
    g_idx[r] = idx;
    out[IDX_OFF + r] = (float)idx;
    out[OH_OFF + (size_t)r * NE + idx] = 1.0f;
    atomicAdd(&g_count[idx], 1);
}

// ---------------------------------------------------------------------------
// z_q gather + straight-through output + loss partials
// out = fl(z_p + fl(z_q - z_p))  -- replicate reference rounding exactly
// ---------------------------------------------------------------------------
__global__ void k_zq_loss(const float* __restrict__ z,
                          const float* __restrict__ emb,
                          float* __restrict__ out) {
    int t = blockIdx.x * 256 + threadIdx.x;     // over B*C*HW in z layout order
    int bi = t >> 18;            // / 262144
    int c  = (t >> 10) & 255;
    int hw = t & 1023;
    int row = (bi << 10) + hw;
    int idx = g_idx[row];
    float e  = emb[(size_t)idx * D + c];
    float zp = z[t];
    float diff = __fadd_rn(e, -zp);              // fl(z_q - z_p)
    out[ZQ_OFF + (size_t)t] = __fadd_rn(zp, diff); // straight-through
    __shared__ double sd[256];
    sd[threadIdx.x] = (double)diff * (double)diff;
    __syncthreads();
    #pragma unroll
    for (int s = 128; s > 0; s >>= 1) {
        if (threadIdx.x < s) sd[threadIdx.x] += sd[threadIdx.x + s];
        __syncthreads();
    }
    if (threadIdx.x == 0) g_losspart[blockIdx.x] = sd[0];
}

__global__ void k_loss_final(float* __restrict__ out) {
    __shared__ double sd[1024];
    double s = 0.0;
    for (int i = threadIdx.x; i < 16384; i += 1024) s += g_losspart[i];
    sd[threadIdx.x] = s;
    __syncthreads();
    #pragma unroll
    for (int st = 512; st > 0; st >>= 1) {
        if (threadIdx.x < st) sd[threadIdx.x] += sd[threadIdx.x + st];
        __syncthreads();
    }
    if (threadIdx.x == 0) {
        float m = (float)(sd[0] / 4194304.0);    // mean((z_q - z_p)^2)
        out[LOSS_OFF] = __fadd_rn(m, __fmul_rn(0.25f, m));  // loss = m + BETA*m
    }
}

__global__ void k_perp(float* __restrict__ out) {
    __shared__ double sd[1024];
    double s = 0.0;
    for (int j = threadIdx.x; j < NE; j += 1024) {
        float p = (float)g_count[j] * (1.0f / 16384.0f);  // exact (pow2 divisor)
        double pd = (double)p;
        s += pd * log(pd + 1e-10);
    }
    sd[threadIdx.x] = s;
    __syncthreads();
    #pragma unroll
    for (int st = 512; st > 0; st >>= 1) {
        if (threadIdx.x < st) sd[threadIdx.x] += sd[threadIdx.x + st];
        __syncthreads();
    }
    if (threadIdx.x == 0) out[PERP_OFF] = (float)exp(-sd[0]);
}

// ---------------------------------------------------------------------------
extern "C" void kernel_launch(void* const* d_in, const int* in_sizes, int n_in,
                              void* d_out, int out_size) {
    const float* z   = (const float*)d_in[0];   // (16,256,32,32)
    const float* emb = (const float*)d_in[1];   // (16384,256)
    float* out = (float*)d_out;

    long long total = (long long)out_size;
    long long n4 = total / 4;

    k_zero<<<8192, 256>>>((float4*)out, n4, out, total);
    k_zero_counts<<<64, 256>>>();
    k_enorm<<<NE / 256, 256>>>(emb);
    k_znorm<<<NROWS / 256, 256>>>(z);

    dim3 g(NROWS / TM, SPLITS);
    k_dist_argmin<<<g, 256>>>(z, emb);

    k_finalize<<<NROWS / 256, 256>>>(out);
    k_zq_loss<<<(NROWS * D) / 256, 256>>>(z, emb, out);
    k_loss_final<<<1, 1024>>>(out);
    k_perp<<<1, 1024>>>(out);
}